// round 10
// baseline (speedup 1.0000x reference)
#include <cuda_runtime.h>
#include <math.h>

// Problem constants (fixed-shape instance)
#define BB 1024
#define SS 512
#define DD 768
#define FF (3*DD)      // 2304
#define H1 256
#define H2 64
#define NC 4
#define BT 8           // batch rows per MLP CTA -> 128 CTAs
#define NT 512         // MLP threads per CTA
#define KT 32          // k-tile rows of W1 per cp.async stage
#define NTILE (FF/KT)  // 72
#define NSTAGE 3       // cp.async ring depth
#define FG 4           // feat kernel row-groups
#define FNT (FG*192)   // 768 feat threads

// Scratch for feat = [e1 | e2 | cls], 1024 x 2304 fp32 (9.4 MB)
__device__ float g_feat[BB * FF];

// ---------------------------------------------------------------------------
// cp.async helpers (LDGSTS)
// ---------------------------------------------------------------------------
__device__ __forceinline__ void cp_async16(float* smem_dst, const float* gmem_src) {
    unsigned s = (unsigned)__cvta_generic_to_shared(smem_dst);
    asm volatile("cp.async.cg.shared.global [%0], [%1], 16;\n" :: "r"(s), "l"(gmem_src));
}
__device__ __forceinline__ void cp_commit() {
    asm volatile("cp.async.commit_group;\n" ::: "memory");
}
template<int N>
__device__ __forceinline__ void cp_wait() {
    asm volatile("cp.async.wait_group %0;\n" :: "n"(N) : "memory");
}

// ---------------------------------------------------------------------------
// Kernel 1: span means + cls. One CTA per batch element, 768 threads =
// 4 row-groups x 192 float4-lanes. At the HBM roofline (~836 MB mandatory
// traffic, ~110% of the 105us floor) — unchanged from R6.
// ---------------------------------------------------------------------------
__global__ __launch_bounds__(FNT) void feat_kernel(
    const float* __restrict__ x,
    const int* __restrict__ e1,
    const int* __restrict__ e2)
{
    __shared__ float4 p1[FG][192];
    __shared__ float4 p2[FG][192];

    const int b    = blockIdx.x;
    const int tid  = threadIdx.x;
    const int g    = tid / 192;
    const int lane = tid % 192;

    int lo1 = e1[2*b]; int hi1 = max(e1[2*b+1], lo1 + 1);
    int lo2 = e2[2*b]; int hi2 = max(e2[2*b+1], lo2 + 1);

    const float4* __restrict__ xb =
        reinterpret_cast<const float4*>(x) + (size_t)b * (SS*(DD/4));

    float4 s1 = make_float4(0.f,0.f,0.f,0.f);
    float4 s2 = make_float4(0.f,0.f,0.f,0.f);

    auto rsum = [&](int a, int c, float4& acc) {
        #pragma unroll 4
        for (int s = a + g; s < c; s += FG) {
            float4 v = __ldcs(&xb[(size_t)s*(DD/4) + lane]);
            acc.x += v.x; acc.y += v.y; acc.z += v.z; acc.w += v.w;
        }
    };

    const int mlo = max(lo1, lo2);
    const int mhi = min(hi1, hi2);
    if (mlo < mhi) {          // overlapping spans: read overlap once
        float4 ov = make_float4(0.f,0.f,0.f,0.f);
        rsum(mlo, mhi, ov);
        rsum(lo1, mlo, s1); rsum(mhi, hi1, s1);
        rsum(lo2, mlo, s2); rsum(mhi, hi2, s2);
        s1.x += ov.x; s1.y += ov.y; s1.z += ov.z; s1.w += ov.w;
        s2.x += ov.x; s2.y += ov.y; s2.z += ov.z; s2.w += ov.w;
    } else {
        rsum(lo1, hi1, s1);
        rsum(lo2, hi2, s2);
    }

    p1[g][lane] = s1;
    p2[g][lane] = s2;
    __syncthreads();

    if (tid < 192) {
        float4 a1 = p1[0][lane], a2 = p2[0][lane];
        #pragma unroll
        for (int gg = 1; gg < FG; ++gg) {
            float4 q1 = p1[gg][lane], q2 = p2[gg][lane];
            a1.x += q1.x; a1.y += q1.y; a1.z += q1.z; a1.w += q1.w;
            a2.x += q2.x; a2.y += q2.y; a2.z += q2.z; a2.w += q2.w;
        }
        const float r1 = 1.f / (float)(hi1 - lo1);
        const float r2 = 1.f / (float)(hi2 - lo2);
        float4 cls = xb[lane];           // row 0 (spans start >= 1)

        float4* __restrict__ fb = reinterpret_cast<float4*>(g_feat + (size_t)b*FF);
        fb[lane]            = make_float4(a1.x*r1, a1.y*r1, a1.z*r1, a1.w*r1);
        fb[(DD/4)   + lane] = make_float4(a2.x*r2, a2.y*r2, a2.z*r2, a2.w*r2);
        fb[2*(DD/4) + lane] = cls;
    }
}

// ---------------------------------------------------------------------------
// Kernel 2: fused 3-layer MLP + softmax. 128 CTAs x 512 threads, BT=8.
// Layer 1: 8x4 register tiles, split-K x8 (tid>>6 = K-group, (tid&63)*4 =
// cols), 3-stage cp.async ring prefetching 2 tiles ahead. Per tile/thread:
// 4 W1 LDS.128 + 8 feat LDS.128(broadcast) + 128 FFMA.
// Dynamic smem: fs [BT*FF] 73728 B + wbuf [3][KT*H1] 98304 B = 172032 B.
// Split-K partials reuse wbuf (drained) - no extra smem.
// ---------------------------------------------------------------------------
__global__ __launch_bounds__(NT) void mlp_kernel(
    const float* __restrict__ W1, const float* __restrict__ b1,
    const float* __restrict__ W2, const float* __restrict__ b2,
    const float* __restrict__ W3, const float* __restrict__ b3,
    float* __restrict__ out)
{
    extern __shared__ float fs[];          // [BT][FF]
    float* wbuf = fs + BT*FF;              // [NSTAGE][KT*H1]
    float* part = wbuf;                    // [7][BT][H1] after drain (57344 B)
    __shared__ float h1s[BT][H1];
    __shared__ float h2s[BT][H2];

    const int b0  = blockIdx.x * BT;
    const int tid = threadIdx.x;

    // --- prologue: commit tiles 0 and 1 ---
    #pragma unroll
    for (int t0 = 0; t0 < 2; ++t0) {
        const float* src = W1 + (size_t)t0*KT*H1;
        float* dst = wbuf + t0*KT*H1;
        #pragma unroll
        for (int i = 0; i < KT*H1/4/NT; ++i)   // 4 float4 per thread
            cp_async16(dst + (tid + i*NT)*4, src + (tid + i*NT)*4);
        cp_commit();
    }

    // --- load feat tile (coalesced float4 copy), overlaps with prefetches ---
    {
        const float4* __restrict__ src =
            reinterpret_cast<const float4*>(g_feat + (size_t)b0 * FF);
        float4* __restrict__ dst = reinterpret_cast<float4*>(fs);
        #pragma unroll
        for (int i = 0; i < BT*FF/4/NT; ++i)   // 9 per thread
            dst[tid + i*NT] = src[tid + i*NT];
    }

    // --- layer 1: [8,2304] @ [2304,256], 8x4 register tiles, split-K x8 ---
    {
        const int kg = tid >> 6;               // 0..7: 4 k-rows of each tile
        const int c0 = (tid & 63) * 4;         // output cols (16B-consecutive)

        float acc[8][4];
        #pragma unroll
        for (int i = 0; i < 8; ++i)
            #pragma unroll
            for (int j = 0; j < 4; ++j) acc[i][j] = 0.f;

        for (int t = 0; t < NTILE; ++t) {
            // tile t was committed 2 iterations ago -> wait is pre-satisfied
            if (t + 1 < NTILE) cp_wait<1>(); else cp_wait<0>();
            __syncthreads();   // tile t visible; all warps done with stage (t+2)%3

            if (t + 2 < NTILE) {   // prefetch 2 ahead, overlaps compute
                const float* src = W1 + (size_t)(t+2)*KT*H1;
                float* dst = wbuf + ((t+2)%NSTAGE)*KT*H1;
                #pragma unroll
                for (int i = 0; i < KT*H1/4/NT; ++i)
                    cp_async16(dst + (tid + i*NT)*4, src + (tid + i*NT)*4);
                cp_commit();
            }

            const float* ws = wbuf + (t%NSTAGE)*KT*H1 + (kg*4)*H1;
            const float* fb = fs + t*KT + kg*4;

            float wv[4][4], fv[8][4];
            #pragma unroll
            for (int q = 0; q < 4; ++q) {
                float4 w = *reinterpret_cast<const float4*>(ws + q*H1 + c0);
                wv[q][0]=w.x; wv[q][1]=w.y; wv[q][2]=w.z; wv[q][3]=w.w;
            }
            #pragma unroll
            for (int i = 0; i < 8; ++i) {
                float4 f = *reinterpret_cast<const float4*>(fb + i*FF);
                fv[i][0]=f.x; fv[i][1]=f.y; fv[i][2]=f.z; fv[i][3]=f.w;
            }
            #pragma unroll
            for (int i = 0; i < 8; ++i)
                #pragma unroll
                for (int q = 0; q < 4; ++q)
                    #pragma unroll
                    for (int j = 0; j < 4; ++j)
                        acc[i][j] = fmaf(fv[i][q], wv[q][j], acc[i][j]);
        }

        // --- cross-kg reduction (partials reuse drained wbuf region) ---
        if (kg > 0) {
            #pragma unroll
            for (int i = 0; i < 8; ++i)
                *reinterpret_cast<float4*>(&part[((kg-1)*BT + i)*H1 + c0]) =
                    make_float4(acc[i][0], acc[i][1], acc[i][2], acc[i][3]);
        }
        __syncthreads();
        if (kg == 0) {
            const float4 bb = *reinterpret_cast<const float4*>(b1 + c0);
            #pragma unroll
            for (int i = 0; i < 8; ++i) {
                float4 s = make_float4(acc[i][0], acc[i][1], acc[i][2], acc[i][3]);
                #pragma unroll
                for (int p = 0; p < 7; ++p) {
                    float4 q = *reinterpret_cast<const float4*>(
                        &part[(p*BT + i)*H1 + c0]);
                    s.x += q.x; s.y += q.y; s.z += q.z; s.w += q.w;
                }
                h1s[i][c0+0] = fmaxf(s.x + bb.x, 0.f);
                h1s[i][c0+1] = fmaxf(s.y + bb.y, 0.f);
                h1s[i][c0+2] = fmaxf(s.z + bb.z, 0.f);
                h1s[i][c0+3] = fmaxf(s.w + bb.w, 0.f);
            }
        }
    }
    __syncthreads();

    // --- layer 2: [8,256] @ [256,64]; one thread per (elem, col) ---
    {
        const int j = tid & (H2-1);
        const int i = tid >> 6;            // 0..7
        float a = 0.f;
        #pragma unroll 4
        for (int k = 0; k < H1; ++k)
            a = fmaf(h1s[i][k], W2[k*H2 + j], a);
        h2s[i][j] = fmaxf(a + b2[j], 0.f);
    }
    __syncthreads();

    // --- layer 3 + softmax: one thread per batch row ---
    if (tid < BT) {
        const int i = tid;
        float l0 = b3[0], l1 = b3[1], l2 = b3[2], l3 = b3[3];
        #pragma unroll 8
        for (int k = 0; k < H2; ++k) {
            const float h = h2s[i][k];
            l0 = fmaf(h, W3[k*NC+0], l0);
            l1 = fmaf(h, W3[k*NC+1], l1);
            l2 = fmaf(h, W3[k*NC+2], l2);
            l3 = fmaf(h, W3[k*NC+3], l3);
        }
        float m = fmaxf(fmaxf(l0,l1), fmaxf(l2,l3));
        float e0 = expf(l0 - m), e1x = expf(l1 - m),
              e2x = expf(l2 - m), e3 = expf(l3 - m);
        float inv = 1.f / (e0 + e1x + e2x + e3);
        float* o = out + (size_t)(b0 + i) * NC;
        o[0] = e0*inv; o[1] = e1x*inv; o[2] = e2x*inv; o[3] = e3*inv;
    }
}

// ---------------------------------------------------------------------------
extern "C" void kernel_launch(void* const* d_in, const int* in_sizes, int n_in,
                              void* d_out, int out_size)
{
    const float* x   = (const float*)d_in[0];
    const int*   e1  = (const int*)  d_in[1];
    const int*   e2  = (const int*)  d_in[2];
    const float* W1  = (const float*)d_in[3];
    const float* b1  = (const float*)d_in[4];
    const float* W2  = (const float*)d_in[5];
    const float* b2  = (const float*)d_in[6];
    const float* W3  = (const float*)d_in[7];
    const float* b3  = (const float*)d_in[8];
    float* out = (float*)d_out;

    static int smem_set = 0;
    const int smem_bytes = (BT*FF + NSTAGE*KT*H1) * (int)sizeof(float);  // 172032
    if (!smem_set) {
        cudaFuncSetAttribute(mlp_kernel,
            cudaFuncAttributeMaxDynamicSharedMemorySize, smem_bytes);
        smem_set = 1;
    }

    feat_kernel<<<BB, FNT>>>(x, e1, e2);
    mlp_kernel<<<BB/BT, NT, smem_bytes>>>(W1, b1, W2, b2, W3, b3, out);
}

// round 13
// speedup vs baseline: 1.0030x; 1.0030x over previous
#include <cuda_runtime.h>
#include <math.h>

// Problem constants (fixed-shape instance)
#define BB 1024
#define SS 512
#define DD 768
#define FF (3*DD)      // 2304
#define H1 256
#define H2 64
#define NC 4
#define BT 8           // batch rows per MLP CTA -> 128 CTAs
#define NT 512         // MLP threads per CTA
#define KT 32          // k-tile rows of W1 per cp.async stage
#define NTILE (FF/KT)  // 72
#define NSTAGE 3       // cp.async ring depth
#define FG 4           // feat kernel row-groups
#define FNT (FG*192)   // 768 feat threads

typedef unsigned long long ull;

// Scratch for feat = [e1 | e2 | cls], 1024 x 2304 fp32 (9.4 MB)
__device__ float g_feat[BB * FF];

// ---------------------------------------------------------------------------
// cp.async helpers (LDGSTS)
// ---------------------------------------------------------------------------
__device__ __forceinline__ void cp_async16(float* smem_dst, const float* gmem_src) {
    unsigned s = (unsigned)__cvta_generic_to_shared(smem_dst);
    asm volatile("cp.async.cg.shared.global [%0], [%1], 16;\n" :: "r"(s), "l"(gmem_src));
}
__device__ __forceinline__ void cp_commit() {
    asm volatile("cp.async.commit_group;\n" ::: "memory");
}
template<int N>
__device__ __forceinline__ void cp_wait() {
    asm volatile("cp.async.wait_group %0;\n" :: "n"(N) : "memory");
}

// ---------------------------------------------------------------------------
// Packed f32x2 helpers (SASS FFMA2 path — only reachable via PTX)
// ---------------------------------------------------------------------------
__device__ __forceinline__ ull pack_dup(float v) {          // (v, v)
    ull r;
    asm("mov.b64 %0, {%1, %1};" : "=l"(r) : "f"(v));
    return r;
}
__device__ __forceinline__ void ffma2(ull& d, ull a, ull b) { // d = a*b + d (2 lanes)
    asm("fma.rn.f32x2 %0, %1, %2, %0;" : "+l"(d) : "l"(a), "l"(b));
}
__device__ __forceinline__ void unpack2(ull v, float& lo, float& hi) {
    asm("mov.b64 {%0, %1}, %2;" : "=f"(lo), "=f"(hi) : "l"(v));
}

// ---------------------------------------------------------------------------
// Kernel 1: span means + cls. One CTA per batch element, 768 threads =
// 4 row-groups x 192 float4-lanes. At the HBM roofline — unchanged.
// ---------------------------------------------------------------------------
__global__ __launch_bounds__(FNT) void feat_kernel(
    const float* __restrict__ x,
    const int* __restrict__ e1,
    const int* __restrict__ e2)
{
    __shared__ float4 p1[FG][192];
    __shared__ float4 p2[FG][192];

    const int b    = blockIdx.x;
    const int tid  = threadIdx.x;
    const int g    = tid / 192;
    const int lane = tid % 192;

    int lo1 = e1[2*b]; int hi1 = max(e1[2*b+1], lo1 + 1);
    int lo2 = e2[2*b]; int hi2 = max(e2[2*b+1], lo2 + 1);

    const float4* __restrict__ xb =
        reinterpret_cast<const float4*>(x) + (size_t)b * (SS*(DD/4));

    float4 s1 = make_float4(0.f,0.f,0.f,0.f);
    float4 s2 = make_float4(0.f,0.f,0.f,0.f);

    auto rsum = [&](int a, int c, float4& acc) {
        #pragma unroll 4
        for (int s = a + g; s < c; s += FG) {
            float4 v = __ldcs(&xb[(size_t)s*(DD/4) + lane]);
            acc.x += v.x; acc.y += v.y; acc.z += v.z; acc.w += v.w;
        }
    };

    const int mlo = max(lo1, lo2);
    const int mhi = min(hi1, hi2);
    if (mlo < mhi) {          // overlapping spans: read overlap once
        float4 ov = make_float4(0.f,0.f,0.f,0.f);
        rsum(mlo, mhi, ov);
        rsum(lo1, mlo, s1); rsum(mhi, hi1, s1);
        rsum(lo2, mlo, s2); rsum(mhi, hi2, s2);
        s1.x += ov.x; s1.y += ov.y; s1.z += ov.z; s1.w += ov.w;
        s2.x += ov.x; s2.y += ov.y; s2.z += ov.z; s2.w += ov.w;
    } else {
        rsum(lo1, hi1, s1);
        rsum(lo2, hi2, s2);
    }

    p1[g][lane] = s1;
    p2[g][lane] = s2;
    __syncthreads();

    if (tid < 192) {
        float4 a1 = p1[0][lane], a2 = p2[0][lane];
        #pragma unroll
        for (int gg = 1; gg < FG; ++gg) {
            float4 q1 = p1[gg][lane], q2 = p2[gg][lane];
            a1.x += q1.x; a1.y += q1.y; a1.z += q1.z; a1.w += q1.w;
            a2.x += q2.x; a2.y += q2.y; a2.z += q2.z; a2.w += q2.w;
        }
        const float r1 = 1.f / (float)(hi1 - lo1);
        const float r2 = 1.f / (float)(hi2 - lo2);
        float4 cls = xb[lane];           // row 0 (spans start >= 1)

        float4* __restrict__ fb = reinterpret_cast<float4*>(g_feat + (size_t)b*FF);
        fb[lane]            = make_float4(a1.x*r1, a1.y*r1, a1.z*r1, a1.w*r1);
        fb[(DD/4)   + lane] = make_float4(a2.x*r2, a2.y*r2, a2.z*r2, a2.w*r2);
        fb[2*(DD/4) + lane] = cls;
    }
}

// ---------------------------------------------------------------------------
// Kernel 2: fused 3-layer MLP + softmax. 128 CTAs x 512 threads, BT=8.
// Layer 1: 8 rows x 4 cols per thread via packed fma.rn.f32x2 (FFMA2):
// 64 FFMA2 + 32 pack-movs per tile per thread (vs 128 FFMA). Split-K x8,
// 3-stage cp.async ring. Dynamic smem: fs 73728 B + wbuf 98304 B.
// ---------------------------------------------------------------------------
__global__ __launch_bounds__(NT) void mlp_kernel(
    const float* __restrict__ W1, const float* __restrict__ b1,
    const float* __restrict__ W2, const float* __restrict__ b2,
    const float* __restrict__ W3, const float* __restrict__ b3,
    float* __restrict__ out)
{
    extern __shared__ float fs[];          // [BT][FF]
    float* wbuf = fs + BT*FF;              // [NSTAGE][KT*H1]
    float* part = wbuf;                    // [7][BT][H1] after drain (57344 B)
    __shared__ float h1s[BT][H1];
    __shared__ float h2s[BT][H2];

    const int b0  = blockIdx.x * BT;
    const int tid = threadIdx.x;

    // --- prologue: commit tiles 0 and 1 ---
    #pragma unroll
    for (int t0 = 0; t0 < 2; ++t0) {
        const float* src = W1 + (size_t)t0*KT*H1;
        float* dst = wbuf + t0*KT*H1;
        #pragma unroll
        for (int i = 0; i < KT*H1/4/NT; ++i)   // 4 float4 per thread
            cp_async16(dst + (tid + i*NT)*4, src + (tid + i*NT)*4);
        cp_commit();
    }

    // --- load feat tile (coalesced float4 copy), overlaps with prefetches ---
    {
        const float4* __restrict__ src =
            reinterpret_cast<const float4*>(g_feat + (size_t)b0 * FF);
        float4* __restrict__ dst = reinterpret_cast<float4*>(fs);
        #pragma unroll
        for (int i = 0; i < BT*FF/4/NT; ++i)   // 9 per thread
            dst[tid + i*NT] = src[tid + i*NT];
    }

    // --- layer 1: [8,2304] @ [2304,256], FFMA2 8x(2x f32x2) tiles, split-K x8 ---
    {
        const int kg = tid >> 6;               // 0..7: 4 k-rows of each tile
        const int c0 = (tid & 63) * 4;         // output cols (16B-consecutive)

        ull accA[8], accB[8];                  // (c0,c0+1) and (c0+2,c0+3)
        #pragma unroll
        for (int i = 0; i < 8; ++i) { accA[i] = 0ull; accB[i] = 0ull; }

        for (int t = 0; t < NTILE; ++t) {
            // tile t was committed 2 iterations ago -> wait is pre-satisfied
            if (t + 1 < NTILE) cp_wait<1>(); else cp_wait<0>();
            __syncthreads();   // tile t visible; all warps done with stage (t+2)%3

            if (t + 2 < NTILE) {   // prefetch 2 ahead, overlaps compute
                const float* src = W1 + (size_t)(t+2)*KT*H1;
                float* dst = wbuf + ((t+2)%NSTAGE)*KT*H1;
                #pragma unroll
                for (int i = 0; i < KT*H1/4/NT; ++i)
                    cp_async16(dst + (tid + i*NT)*4, src + (tid + i*NT)*4);
                cp_commit();
            }

            const float* ws = wbuf + (t%NSTAGE)*KT*H1 + (kg*4)*H1;
            const float* fb = fs + t*KT + kg*4;

            // W1 column pairs as 64-bit lanes (consecutive cols c0..c0+3)
            ull wA[4], wB[4];
            #pragma unroll
            for (int q = 0; q < 4; ++q) {
                const ull* w2 = reinterpret_cast<const ull*>(ws + q*H1 + c0);
                wA[q] = w2[0];
                wB[q] = w2[1];
            }
            float4 fv[8];
            #pragma unroll
            for (int i = 0; i < 8; ++i)
                fv[i] = *reinterpret_cast<const float4*>(fb + i*FF);

            #pragma unroll
            for (int i = 0; i < 8; ++i) {
                ull p0 = pack_dup(fv[i].x);
                ull p1 = pack_dup(fv[i].y);
                ull p2 = pack_dup(fv[i].z);
                ull p3 = pack_dup(fv[i].w);
                ffma2(accA[i], p0, wA[0]);  ffma2(accB[i], p0, wB[0]);
                ffma2(accA[i], p1, wA[1]);  ffma2(accB[i], p1, wB[1]);
                ffma2(accA[i], p2, wA[2]);  ffma2(accB[i], p2, wB[2]);
                ffma2(accA[i], p3, wA[3]);  ffma2(accB[i], p3, wB[3]);
            }
        }

        // --- cross-kg reduction (partials reuse drained wbuf region) ---
        if (kg > 0) {
            #pragma unroll
            for (int i = 0; i < 8; ++i) {
                float a0,a1,a2,a3;
                unpack2(accA[i], a0, a1);
                unpack2(accB[i], a2, a3);
                *reinterpret_cast<float4*>(&part[((kg-1)*BT + i)*H1 + c0]) =
                    make_float4(a0, a1, a2, a3);
            }
        }
        __syncthreads();
        if (kg == 0) {
            const float4 bb = *reinterpret_cast<const float4*>(b1 + c0);
            #pragma unroll
            for (int i = 0; i < 8; ++i) {
                float a0,a1,a2,a3;
                unpack2(accA[i], a0, a1);
                unpack2(accB[i], a2, a3);
                float4 s = make_float4(a0, a1, a2, a3);
                #pragma unroll
                for (int p = 0; p < 7; ++p) {
                    float4 q = *reinterpret_cast<const float4*>(
                        &part[(p*BT + i)*H1 + c0]);
                    s.x += q.x; s.y += q.y; s.z += q.z; s.w += q.w;
                }
                h1s[i][c0+0] = fmaxf(s.x + bb.x, 0.f);
                h1s[i][c0+1] = fmaxf(s.y + bb.y, 0.f);
                h1s[i][c0+2] = fmaxf(s.z + bb.z, 0.f);
                h1s[i][c0+3] = fmaxf(s.w + bb.w, 0.f);
            }
        }
    }
    __syncthreads();

    // --- layer 2: [8,256] @ [256,64]; one thread per (elem, col) ---
    {
        const int j = tid & (H2-1);
        const int i = tid >> 6;            // 0..7
        float a = 0.f;
        #pragma unroll 4
        for (int k = 0; k < H1; ++k)
            a = fmaf(h1s[i][k], W2[k*H2 + j], a);
        h2s[i][j] = fmaxf(a + b2[j], 0.f);
    }
    __syncthreads();

    // --- layer 3 + softmax: one thread per batch row ---
    if (tid < BT) {
        const int i = tid;
        float l0 = b3[0], l1 = b3[1], l2 = b3[2], l3 = b3[3];
        #pragma unroll 8
        for (int k = 0; k < H2; ++k) {
            const float h = h2s[i][k];
            l0 = fmaf(h, W3[k*NC+0], l0);
            l1 = fmaf(h, W3[k*NC+1], l1);
            l2 = fmaf(h, W3[k*NC+2], l2);
            l3 = fmaf(h, W3[k*NC+3], l3);
        }
        float m = fmaxf(fmaxf(l0,l1), fmaxf(l2,l3));
        float e0 = expf(l0 - m), e1x = expf(l1 - m),
              e2x = expf(l2 - m), e3 = expf(l3 - m);
        float inv = 1.f / (e0 + e1x + e2x + e3);
        float* o = out + (size_t)(b0 + i) * NC;
        o[0] = e0*inv; o[1] = e1x*inv; o[2] = e2x*inv; o[3] = e3*inv;
    }
}

// ---------------------------------------------------------------------------
extern "C" void kernel_launch(void* const* d_in, const int* in_sizes, int n_in,
                              void* d_out, int out_size)
{
    const float* x   = (const float*)d_in[0];
    const int*   e1  = (const int*)  d_in[1];
    const int*   e2  = (const int*)  d_in[2];
    const float* W1  = (const float*)d_in[3];
    const float* b1  = (const float*)d_in[4];
    const float* W2  = (const float*)d_in[5];
    const float* b2  = (const float*)d_in[6];
    const float* W3  = (const float*)d_in[7];
    const float* b3  = (const float*)d_in[8];
    float* out = (float*)d_out;

    static int smem_set = 0;
    const int smem_bytes = (BT*FF + NSTAGE*KT*H1) * (int)sizeof(float);  // 172032
    if (!smem_set) {
        cudaFuncSetAttribute(mlp_kernel,
            cudaFuncAttributeMaxDynamicSharedMemorySize, smem_bytes);
        smem_set = 1;
    }

    feat_kernel<<<BB, FNT>>>(x, e1, e2);
    mlp_kernel<<<BB/BT, NT, smem_bytes>>>(W1, b1, W2, b2, W3, b3, out);
}

// round 15
// speedup vs baseline: 1.2148x; 1.2111x over previous
#include <cuda_runtime.h>
#include <cuda_bf16.h>
#include <math.h>
#include <stdint.h>

// Problem constants
#define BB 1024
#define SS 512
#define DD 768
#define FF (3*DD)      // 2304
#define H1 256
#define H2 64
#define NC 4
#define FG 4           // feat kernel row-groups
#define FNT (FG*192)   // 768 feat threads

// GEMM tiling
#define MT 128         // M rows per CTA
#define KC 128         // K per CTA (split-K)
#define KSPLIT 18      // 18 * 128 = 2304
#define MTILES 8       // 8 * 128 = 1024
#define AS 136         // A smem row stride (elements): 272B -> conflict-free ldmatrix
#define BS 136         // B smem row stride

// Device scratch (no cudaMalloc allowed)
__device__ __nv_bfloat16 g_Abf[BB * FF];      // feat, bf16 [1024][2304] row-major (k contig)
__device__ __nv_bfloat16 g_Bbf[H1 * FF];      // W1^T,  bf16 [256 n][2304 k] (k contig)
__device__ float g_part[KSPLIT * BB * H1];    // split-K partials (18.9 MB)

// ---------------------------------------------------------------------------
// PTX helpers (all plain sm_80+/sm_75+ features -> legal on compute_103)
// ---------------------------------------------------------------------------
__device__ __forceinline__ void cp_async16(void* smem_dst, const void* gmem_src) {
    unsigned s = (unsigned)__cvta_generic_to_shared(smem_dst);
    asm volatile("cp.async.cg.shared.global [%0], [%1], 16;\n" :: "r"(s), "l"(gmem_src));
}
__device__ __forceinline__ void cp_commit() {
    asm volatile("cp.async.commit_group;\n" ::: "memory");
}
template<int N>
__device__ __forceinline__ void cp_wait() {
    asm volatile("cp.async.wait_group %0;\n" :: "n"(N) : "memory");
}
__device__ __forceinline__ uint32_t smem_u32(const void* p) {
    return (uint32_t)__cvta_generic_to_shared(p);
}
__device__ __forceinline__ void ldsm_x4(uint32_t& r0, uint32_t& r1,
                                        uint32_t& r2, uint32_t& r3, uint32_t addr) {
    asm volatile("ldmatrix.sync.aligned.m8n8.x4.shared.b16 {%0,%1,%2,%3}, [%4];"
        : "=r"(r0), "=r"(r1), "=r"(r2), "=r"(r3) : "r"(addr));
}
__device__ __forceinline__ void mma16816(float* d, const uint32_t* a,
                                         const uint32_t* b) {
    asm volatile(
        "mma.sync.aligned.m16n8k16.row.col.f32.bf16.bf16.f32 "
        "{%0,%1,%2,%3}, {%4,%5,%6,%7}, {%8,%9}, {%0,%1,%2,%3};"
        : "+f"(d[0]), "+f"(d[1]), "+f"(d[2]), "+f"(d[3])
        : "r"(a[0]), "r"(a[1]), "r"(a[2]), "r"(a[3]), "r"(b[0]), "r"(b[1]));
}

// ---------------------------------------------------------------------------
// Kernel 1: span means + cls -> bf16 A matrix. One CTA per batch element,
// 768 threads = 4 row-groups x 192 float4-lanes (HBM-bound, unchanged walk).
// ---------------------------------------------------------------------------
__global__ __launch_bounds__(FNT) void feat_kernel(
    const float* __restrict__ x,
    const int* __restrict__ e1,
    const int* __restrict__ e2)
{
    __shared__ float4 p1[FG][192];
    __shared__ float4 p2[FG][192];

    const int b    = blockIdx.x;
    const int tid  = threadIdx.x;
    const int g    = tid / 192;
    const int lane = tid % 192;

    int lo1 = e1[2*b]; int hi1 = max(e1[2*b+1], lo1 + 1);
    int lo2 = e2[2*b]; int hi2 = max(e2[2*b+1], lo2 + 1);

    const float4* __restrict__ xb =
        reinterpret_cast<const float4*>(x) + (size_t)b * (SS*(DD/4));

    float4 s1 = make_float4(0.f,0.f,0.f,0.f);
    float4 s2 = make_float4(0.f,0.f,0.f,0.f);

    auto rsum = [&](int a, int c, float4& acc) {
        #pragma unroll 4
        for (int s = a + g; s < c; s += FG) {
            float4 v = __ldcs(&xb[(size_t)s*(DD/4) + lane]);
            acc.x += v.x; acc.y += v.y; acc.z += v.z; acc.w += v.w;
        }
    };

    const int mlo = max(lo1, lo2);
    const int mhi = min(hi1, hi2);
    if (mlo < mhi) {          // overlapping spans: read overlap once
        float4 ov = make_float4(0.f,0.f,0.f,0.f);
        rsum(mlo, mhi, ov);
        rsum(lo1, mlo, s1); rsum(mhi, hi1, s1);
        rsum(lo2, mlo, s2); rsum(mhi, hi2, s2);
        s1.x += ov.x; s1.y += ov.y; s1.z += ov.z; s1.w += ov.w;
        s2.x += ov.x; s2.y += ov.y; s2.z += ov.z; s2.w += ov.w;
    } else {
        rsum(lo1, hi1, s1);
        rsum(lo2, hi2, s2);
    }

    p1[g][lane] = s1;
    p2[g][lane] = s2;
    __syncthreads();

    if (tid < 192) {
        float4 a1 = p1[0][lane], a2 = p2[0][lane];
        #pragma unroll
        for (int gg = 1; gg < FG; ++gg) {
            float4 q1 = p1[gg][lane], q2 = p2[gg][lane];
            a1.x += q1.x; a1.y += q1.y; a1.z += q1.z; a1.w += q1.w;
            a2.x += q2.x; a2.y += q2.y; a2.z += q2.z; a2.w += q2.w;
        }
        const float r1 = 1.f / (float)(hi1 - lo1);
        const float r2 = 1.f / (float)(hi2 - lo2);
        float4 cls = xb[lane];           // row 0 (spans start >= 1)

        auto pack4 = [](float a, float b, float c, float d) {
            uint2 r;
            r.x = ((uint32_t)__bfloat16_as_ushort(__float2bfloat16_rn(b)) << 16)
                |  (uint32_t)__bfloat16_as_ushort(__float2bfloat16_rn(a));
            r.y = ((uint32_t)__bfloat16_as_ushort(__float2bfloat16_rn(d)) << 16)
                |  (uint32_t)__bfloat16_as_ushort(__float2bfloat16_rn(c));
            return r;
        };

        uint2* __restrict__ ab = reinterpret_cast<uint2*>(g_Abf) + (size_t)b*(FF/4);
        ab[lane]       = pack4(a1.x*r1, a1.y*r1, a1.z*r1, a1.w*r1);
        ab[192 + lane] = pack4(a2.x*r2, a2.y*r2, a2.z*r2, a2.w*r2);
        ab[384 + lane] = pack4(cls.x, cls.y, cls.z, cls.w);
    }
}

// ---------------------------------------------------------------------------
// Kernel 2: W1 [2304,256] fp32 -> g_Bbf [256][2304] bf16 (transposed).
// ---------------------------------------------------------------------------
__global__ __launch_bounds__(256) void wconv_kernel(const float* __restrict__ W1)
{
    __shared__ float sb[64][65];
    const int k0 = blockIdx.x * 64;
    const int n0 = blockIdx.y * 64;
    const int t  = threadIdx.x;
    const int c  = t & 63;
    const int rb = t >> 6;           // 0..3

    #pragma unroll
    for (int rr = 0; rr < 16; ++rr) {
        const int r = rb + rr*4;     // 0..63
        sb[r][c] = W1[(size_t)(k0 + r) * H1 + n0 + c];
    }
    __syncthreads();
    #pragma unroll
    for (int rr = 0; rr < 16; ++rr) {
        const int n = rb + rr*4;     // local n 0..63
        g_Bbf[(size_t)(n0 + n) * FF + k0 + c] = __float2bfloat16_rn(sb[c][n]);
    }
}

// ---------------------------------------------------------------------------
// Kernel 3: bf16 HMMA GEMM, split-K. grid (MTILES=8, KSPLIT=18), 512 threads.
// CTA (mt, ks): C_partial[mt*128..+128, 0..256) over K [ks*128, +128).
// SMEM: As[128][136] bf16 (34816 B) + Bs[256][136] bf16 (69632 B).
// 16 warps, warp tile M64 x N32: per k16-step 4 A-ldmatrix.x4 +
// 2 B-ldmatrix.x4 + 16 mma.m16n8k16.
// ---------------------------------------------------------------------------
__global__ __launch_bounds__(512) void gemm_kernel()
{
    extern __shared__ __nv_bfloat16 sm[];
    __nv_bfloat16* As = sm;                 // [128][AS]
    __nv_bfloat16* Bsm = sm + MT*AS;        // [256][BS]

    const int tid    = threadIdx.x;
    const int wid    = tid >> 5;
    const int lane   = tid & 31;
    const int warp_m = wid >> 3;            // 0..1  (64 rows each)
    const int warp_n = wid & 7;             // 0..7  (32 cols each)
    const int m0     = blockIdx.x * MT;
    const int ks     = blockIdx.y;
    const int k0     = ks * KC;

    // --- load A[128][128] : 2048 16B-segs, 4 per thread ---
    #pragma unroll
    for (int i = 0; i < 4; ++i) {
        const int idx = tid + i*512;        // 0..2047
        const int row = idx >> 4;
        const int seg = idx & 15;
        cp_async16(As + row*AS + seg*8,
                   g_Abf + (size_t)(m0 + row)*FF + k0 + seg*8);
    }
    // --- load B[256][128] : 4096 segs, 8 per thread ---
    #pragma unroll
    for (int i = 0; i < 8; ++i) {
        const int idx = tid + i*512;        // 0..4095
        const int row = idx >> 4;
        const int seg = idx & 15;
        cp_async16(Bsm + row*BS + seg*8,
                   g_Bbf + (size_t)row*FF + k0 + seg*8);
    }
    cp_commit();
    cp_wait<0>();
    __syncthreads();

    // --- per-thread ldmatrix base addresses (bytes) ---
    // A frag (m16 x k16): lanes 0-15 -> rows 0..15 at kk, lanes 16-31 -> +8 cols
    uint32_t a_addr[4];
    #pragma unroll
    for (int mt = 0; mt < 4; ++mt)
        a_addr[mt] = smem_u32(As) +
            (uint32_t)(((warp_m*64 + mt*16 + (lane & 15))*AS + (lane >> 4)*8) * 2);
    // B frags (two n16 groups): lanes0-7 n0-7@kk, 8-15 n0-7@kk+8, 16-23 n8-15@kk, 24-31 n8-15@kk+8
    uint32_t b_addr[2];
    #pragma unroll
    for (int ng = 0; ng < 2; ++ng)
        b_addr[ng] = smem_u32(Bsm) +
            (uint32_t)(((warp_n*32 + ng*16 + (lane & 7) + ((lane >> 4) << 3))*BS
                        + ((lane >> 3) & 1)*8) * 2);

    float acc[4][4][4];
    #pragma unroll
    for (int mt = 0; mt < 4; ++mt)
        #pragma unroll
        for (int nt = 0; nt < 4; ++nt)
            #pragma unroll
            for (int r = 0; r < 4; ++r) acc[mt][nt][r] = 0.f;

    #pragma unroll
    for (int kk = 0; kk < KC; kk += 16) {
        uint32_t a[4][4], b[2][4];
        #pragma unroll
        for (int mt = 0; mt < 4; ++mt)
            ldsm_x4(a[mt][0], a[mt][1], a[mt][2], a[mt][3], a_addr[mt] + kk*2);
        #pragma unroll
        for (int ng = 0; ng < 2; ++ng)
            ldsm_x4(b[ng][0], b[ng][1], b[ng][2], b[ng][3], b_addr[ng] + kk*2);

        #pragma unroll
        for (int mt = 0; mt < 4; ++mt)
            #pragma unroll
            for (int nt = 0; nt < 4; ++nt)
                mma16816(acc[mt][nt], a[mt], b[nt >> 1] + (nt & 1)*2);
    }

    // --- epilogue: write partials (fp32) ---
    // c-frag mapping: d0,d1 -> row (lane>>2), cols 2*(lane&3)+{0,1}; d2,d3 -> row+8
    const int ep_r = lane >> 2;
    const int ep_c = (lane & 3) * 2;
    #pragma unroll
    for (int mt = 0; mt < 4; ++mt) {
        #pragma unroll
        for (int nt = 0; nt < 4; ++nt) {
            const int row = m0 + warp_m*64 + mt*16 + ep_r;
            const int col = warp_n*32 + nt*8 + ep_c;
            float* dst = g_part + ((size_t)ks * BB + row) * H1 + col;
            *reinterpret_cast<float2*>(dst) =
                make_float2(acc[mt][nt][0], acc[mt][nt][1]);
            *reinterpret_cast<float2*>(dst + 8*H1) =
                make_float2(acc[mt][nt][2], acc[mt][nt][3]);
        }
    }
}

// ---------------------------------------------------------------------------
// Kernel 4: reduce split-K partials + bias/relu (h1), layer 2, layer 3,
// softmax. 128 CTAs x 256 threads, 8 batch rows each.
// ---------------------------------------------------------------------------
__global__ __launch_bounds__(256) void tail_kernel(
    const float* __restrict__ b1,
    const float* __restrict__ W2, const float* __restrict__ b2,
    const float* __restrict__ W3, const float* __restrict__ b3,
    float* __restrict__ out)
{
    __shared__ float h1s[8][H1];
    __shared__ float h2s[8][H2];

    const int b0  = blockIdx.x * 8;
    const int tid = threadIdx.x;

    // --- h1 = relu(b1 + sum_ks partial) ---
    {
        const int c = tid;               // 0..255
        const float bb = b1[c];
        #pragma unroll
        for (int i = 0; i < 8; ++i) {
            float s = bb;
            #pragma unroll
            for (int ks = 0; ks < KSPLIT; ++ks)
                s += g_part[((size_t)ks * BB + b0 + i) * H1 + c];
            h1s[i][c] = fmaxf(s, 0.f);
        }
    }
    __syncthreads();

    // --- layer 2: [8,256] @ [256,64]; thread -> (j, 2 rows) ---
    {
        const int j  = tid & (H2-1);
        const int i0 = (tid >> 6) * 2;
        float a0 = 0.f, a1 = 0.f;
        #pragma unroll 4
        for (int k = 0; k < H1; ++k) {
            const float w = W2[k*H2 + j];
            a0 = fmaf(h1s[i0+0][k], w, a0);
            a1 = fmaf(h1s[i0+1][k], w, a1);
        }
        const float bb = b2[j];
        h2s[i0+0][j] = fmaxf(a0 + bb, 0.f);
        h2s[i0+1][j] = fmaxf(a1 + bb, 0.f);
    }
    __syncthreads();

    // --- layer 3 + softmax ---
    if (tid < 8) {
        const int i = tid;
        float l0 = b3[0], l1 = b3[1], l2 = b3[2], l3 = b3[3];
        #pragma unroll 8
        for (int k = 0; k < H2; ++k) {
            const float h = h2s[i][k];
            l0 = fmaf(h, W3[k*NC+0], l0);
            l1 = fmaf(h, W3[k*NC+1], l1);
            l2 = fmaf(h, W3[k*NC+2], l2);
            l3 = fmaf(h, W3[k*NC+3], l3);
        }
        float m = fmaxf(fmaxf(l0,l1), fmaxf(l2,l3));
        float e0 = expf(l0 - m), e1x = expf(l1 - m),
              e2x = expf(l2 - m), e3 = expf(l3 - m);
        float inv = 1.f / (e0 + e1x + e2x + e3);
        float* o = out + (size_t)(b0 + i) * NC;
        o[0] = e0*inv; o[1] = e1x*inv; o[2] = e2x*inv; o[3] = e3*inv;
    }
}

// ---------------------------------------------------------------------------
extern "C" void kernel_launch(void* const* d_in, const int* in_sizes, int n_in,
                              void* d_out, int out_size)
{
    const float* x   = (const float*)d_in[0];
    const int*   e1  = (const int*)  d_in[1];
    const int*   e2  = (const int*)  d_in[2];
    const float* W1  = (const float*)d_in[3];
    const float* b1  = (const float*)d_in[4];
    const float* W2  = (const float*)d_in[5];
    const float* b2  = (const float*)d_in[6];
    const float* W3  = (const float*)d_in[7];
    const float* b3  = (const float*)d_in[8];
    float* out = (float*)d_out;

    static int smem_set = 0;
    const int gemm_smem = (MT*AS + H1*BS) * (int)sizeof(__nv_bfloat16);  // 104448
    if (!smem_set) {
        cudaFuncSetAttribute(gemm_kernel,
            cudaFuncAttributeMaxDynamicSharedMemorySize, gemm_smem);
        smem_set = 1;
    }

    feat_kernel<<<BB, FNT>>>(x, e1, e2);
    wconv_kernel<<<dim3(FF/64, H1/64), 256>>>(W1);
    gemm_kernel<<<dim3(MTILES, KSPLIT), 512, gemm_smem>>>();
    tail_kernel<<<BB/8, 256>>>(b1, W2, b2, W3, b3, out);
}

// round 16
// speedup vs baseline: 1.2470x; 1.0265x over previous
#include <cuda_runtime.h>
#include <cuda_bf16.h>
#include <math.h>
#include <stdint.h>

// Problem constants
#define BB 1024
#define SS 512
#define DD 768
#define FF (3*DD)      // 2304
#define H1 256
#define H2 64
#define NC 4
#define FG 4           // feat kernel row-groups
#define FNT (FG*192)   // 768 feat threads

// GEMM tiling
#define MT 128         // M rows per CTA
#define KC 128         // K per CTA (split-K)
#define KSPLIT 18      // 18 * 128 = 2304
#define MTILES 8       // 8 * 128 = 1024
#define AS 136         // A smem row stride (elements)
#define BS 136         // B smem row stride

// Device scratch (no cudaMalloc allowed)
__device__ __nv_bfloat16 g_Abf[BB * FF];      // feat, bf16 [1024][2304]
__device__ __nv_bfloat16 g_Bbf[H1 * FF];      // W1^T,  bf16 [256][2304]
__device__ float g_part[KSPLIT * BB * H1];    // split-K partials (18.9 MB)
__device__ float g_h1[BB * H1];               // relu(layer1) (1 MB)

// ---------------------------------------------------------------------------
// PTX helpers (plain sm_80+/75+ features -> legal on compute_103)
// ---------------------------------------------------------------------------
__device__ __forceinline__ void cp_async16(void* smem_dst, const void* gmem_src) {
    unsigned s = (unsigned)__cvta_generic_to_shared(smem_dst);
    asm volatile("cp.async.cg.shared.global [%0], [%1], 16;\n" :: "r"(s), "l"(gmem_src));
}
__device__ __forceinline__ void cp_commit() {
    asm volatile("cp.async.commit_group;\n" ::: "memory");
}
template<int N>
__device__ __forceinline__ void cp_wait() {
    asm volatile("cp.async.wait_group %0;\n" :: "n"(N) : "memory");
}
__device__ __forceinline__ uint32_t smem_u32(const void* p) {
    return (uint32_t)__cvta_generic_to_shared(p);
}
__device__ __forceinline__ void ldsm_x4(uint32_t& r0, uint32_t& r1,
                                        uint32_t& r2, uint32_t& r3, uint32_t addr) {
    asm volatile("ldmatrix.sync.aligned.m8n8.x4.shared.b16 {%0,%1,%2,%3}, [%4];"
        : "=r"(r0), "=r"(r1), "=r"(r2), "=r"(r3) : "r"(addr));
}
__device__ __forceinline__ void mma16816(float* d, const uint32_t* a,
                                         const uint32_t* b) {
    asm volatile(
        "mma.sync.aligned.m16n8k16.row.col.f32.bf16.bf16.f32 "
        "{%0,%1,%2,%3}, {%4,%5,%6,%7}, {%8,%9}, {%0,%1,%2,%3};"
        : "+f"(d[0]), "+f"(d[1]), "+f"(d[2]), "+f"(d[3])
        : "r"(a[0]), "r"(a[1]), "r"(a[2]), "r"(a[3]), "r"(b[0]), "r"(b[1]));
}

// ---------------------------------------------------------------------------
// Kernel 1: span means + cls -> bf16 A matrix (HBM-bound, unchanged).
// ---------------------------------------------------------------------------
__global__ __launch_bounds__(FNT) void feat_kernel(
    const float* __restrict__ x,
    const int* __restrict__ e1,
    const int* __restrict__ e2)
{
    __shared__ float4 p1[FG][192];
    __shared__ float4 p2[FG][192];

    const int b    = blockIdx.x;
    const int tid  = threadIdx.x;
    const int g    = tid / 192;
    const int lane = tid % 192;

    int lo1 = e1[2*b]; int hi1 = max(e1[2*b+1], lo1 + 1);
    int lo2 = e2[2*b]; int hi2 = max(e2[2*b+1], lo2 + 1);

    const float4* __restrict__ xb =
        reinterpret_cast<const float4*>(x) + (size_t)b * (SS*(DD/4));

    float4 s1 = make_float4(0.f,0.f,0.f,0.f);
    float4 s2 = make_float4(0.f,0.f,0.f,0.f);

    auto rsum = [&](int a, int c, float4& acc) {
        #pragma unroll 4
        for (int s = a + g; s < c; s += FG) {
            float4 v = __ldcs(&xb[(size_t)s*(DD/4) + lane]);
            acc.x += v.x; acc.y += v.y; acc.z += v.z; acc.w += v.w;
        }
    };

    const int mlo = max(lo1, lo2);
    const int mhi = min(hi1, hi2);
    if (mlo < mhi) {          // overlapping spans: read overlap once
        float4 ov = make_float4(0.f,0.f,0.f,0.f);
        rsum(mlo, mhi, ov);
        rsum(lo1, mlo, s1); rsum(mhi, hi1, s1);
        rsum(lo2, mlo, s2); rsum(mhi, hi2, s2);
        s1.x += ov.x; s1.y += ov.y; s1.z += ov.z; s1.w += ov.w;
        s2.x += ov.x; s2.y += ov.y; s2.z += ov.z; s2.w += ov.w;
    } else {
        rsum(lo1, hi1, s1);
        rsum(lo2, hi2, s2);
    }

    p1[g][lane] = s1;
    p2[g][lane] = s2;
    __syncthreads();

    if (tid < 192) {
        float4 a1 = p1[0][lane], a2 = p2[0][lane];
        #pragma unroll
        for (int gg = 1; gg < FG; ++gg) {
            float4 q1 = p1[gg][lane], q2 = p2[gg][lane];
            a1.x += q1.x; a1.y += q1.y; a1.z += q1.z; a1.w += q1.w;
            a2.x += q2.x; a2.y += q2.y; a2.z += q2.z; a2.w += q2.w;
        }
        const float r1 = 1.f / (float)(hi1 - lo1);
        const float r2 = 1.f / (float)(hi2 - lo2);
        float4 cls = xb[lane];           // row 0 (spans start >= 1)

        auto pack4 = [](float a, float b, float c, float d) {
            uint2 r;
            r.x = ((uint32_t)__bfloat16_as_ushort(__float2bfloat16_rn(b)) << 16)
                |  (uint32_t)__bfloat16_as_ushort(__float2bfloat16_rn(a));
            r.y = ((uint32_t)__bfloat16_as_ushort(__float2bfloat16_rn(d)) << 16)
                |  (uint32_t)__bfloat16_as_ushort(__float2bfloat16_rn(c));
            return r;
        };

        uint2* __restrict__ ab = reinterpret_cast<uint2*>(g_Abf) + (size_t)b*(FF/4);
        ab[lane]       = pack4(a1.x*r1, a1.y*r1, a1.z*r1, a1.w*r1);
        ab[192 + lane] = pack4(a2.x*r2, a2.y*r2, a2.z*r2, a2.w*r2);
        ab[384 + lane] = pack4(cls.x, cls.y, cls.z, cls.w);
    }
}

// ---------------------------------------------------------------------------
// Kernel 2: W1 [2304,256] fp32 -> g_Bbf [256][2304] bf16 (transposed).
// ---------------------------------------------------------------------------
__global__ __launch_bounds__(256) void wconv_kernel(const float* __restrict__ W1)
{
    __shared__ float sb[64][65];
    const int k0 = blockIdx.x * 64;
    const int n0 = blockIdx.y * 64;
    const int t  = threadIdx.x;
    const int c  = t & 63;
    const int rb = t >> 6;           // 0..3

    #pragma unroll
    for (int rr = 0; rr < 16; ++rr) {
        const int r = rb + rr*4;     // 0..63
        sb[r][c] = W1[(size_t)(k0 + r) * H1 + n0 + c];
    }
    __syncthreads();
    #pragma unroll
    for (int rr = 0; rr < 16; ++rr) {
        const int n = rb + rr*4;     // local n 0..63
        g_Bbf[(size_t)(n0 + n) * FF + k0 + c] = __float2bfloat16_rn(sb[c][n]);
    }
}

// ---------------------------------------------------------------------------
// Kernel 3: bf16 HMMA GEMM, split-K. grid (8, 18), 512 threads. Unchanged.
// ---------------------------------------------------------------------------
__global__ __launch_bounds__(512) void gemm_kernel()
{
    extern __shared__ __nv_bfloat16 sm[];
    __nv_bfloat16* As = sm;                 // [128][AS]
    __nv_bfloat16* Bsm = sm + MT*AS;        // [256][BS]

    const int tid    = threadIdx.x;
    const int wid    = tid >> 5;
    const int lane   = tid & 31;
    const int warp_m = wid >> 3;            // 0..1
    const int warp_n = wid & 7;             // 0..7
    const int m0     = blockIdx.x * MT;
    const int ks     = blockIdx.y;
    const int k0     = ks * KC;

    #pragma unroll
    for (int i = 0; i < 4; ++i) {
        const int idx = tid + i*512;
        const int row = idx >> 4;
        const int seg = idx & 15;
        cp_async16(As + row*AS + seg*8,
                   g_Abf + (size_t)(m0 + row)*FF + k0 + seg*8);
    }
    #pragma unroll
    for (int i = 0; i < 8; ++i) {
        const int idx = tid + i*512;
        const int row = idx >> 4;
        const int seg = idx & 15;
        cp_async16(Bsm + row*BS + seg*8,
                   g_Bbf + (size_t)row*FF + k0 + seg*8);
    }
    cp_commit();
    cp_wait<0>();
    __syncthreads();

    uint32_t a_addr[4];
    #pragma unroll
    for (int mt = 0; mt < 4; ++mt)
        a_addr[mt] = smem_u32(As) +
            (uint32_t)(((warp_m*64 + mt*16 + (lane & 15))*AS + (lane >> 4)*8) * 2);
    uint32_t b_addr[2];
    #pragma unroll
    for (int ng = 0; ng < 2; ++ng)
        b_addr[ng] = smem_u32(Bsm) +
            (uint32_t)(((warp_n*32 + ng*16 + (lane & 7) + ((lane >> 4) << 3))*BS
                        + ((lane >> 3) & 1)*8) * 2);

    float acc[4][4][4];
    #pragma unroll
    for (int mt = 0; mt < 4; ++mt)
        #pragma unroll
        for (int nt = 0; nt < 4; ++nt)
            #pragma unroll
            for (int r = 0; r < 4; ++r) acc[mt][nt][r] = 0.f;

    #pragma unroll
    for (int kk = 0; kk < KC; kk += 16) {
        uint32_t a[4][4], b[2][4];
        #pragma unroll
        for (int mt = 0; mt < 4; ++mt)
            ldsm_x4(a[mt][0], a[mt][1], a[mt][2], a[mt][3], a_addr[mt] + kk*2);
        #pragma unroll
        for (int ng = 0; ng < 2; ++ng)
            ldsm_x4(b[ng][0], b[ng][1], b[ng][2], b[ng][3], b_addr[ng] + kk*2);

        #pragma unroll
        for (int mt = 0; mt < 4; ++mt)
            #pragma unroll
            for (int nt = 0; nt < 4; ++nt)
                mma16816(acc[mt][nt], a[mt], b[nt >> 1] + (nt & 1)*2);
    }

    const int ep_r = lane >> 2;
    const int ep_c = (lane & 3) * 2;
    #pragma unroll
    for (int mt = 0; mt < 4; ++mt) {
        #pragma unroll
        for (int nt = 0; nt < 4; ++nt) {
            const int row = m0 + warp_m*64 + mt*16 + ep_r;
            const int col = warp_n*32 + nt*8 + ep_c;
            float* dst = g_part + ((size_t)ks * BB + row) * H1 + col;
            *reinterpret_cast<float2*>(dst) =
                make_float2(acc[mt][nt][0], acc[mt][nt][1]);
            *reinterpret_cast<float2*>(dst + 8*H1) =
                make_float2(acc[mt][nt][2], acc[mt][nt][3]);
        }
    }
}

// ---------------------------------------------------------------------------
// Kernel 4: split-K reduction + bias + relu -> g_h1. One CTA per batch row,
// 256 threads (one per h1 column). 262K threads, fully coalesced: HBM-bound.
// ---------------------------------------------------------------------------
__global__ __launch_bounds__(256) void reduce_kernel(const float* __restrict__ b1)
{
    const int b = blockIdx.x;
    const int c = threadIdx.x;
    float s = b1[c];
    #pragma unroll
    for (int ks = 0; ks < KSPLIT; ++ks)
        s += g_part[((size_t)ks * BB + b) * H1 + c];
    g_h1[(size_t)b * H1 + c] = fmaxf(s, 0.f);
}

// ---------------------------------------------------------------------------
// Kernel 5: layers 2/3 + softmax. 256 CTAs x 256 threads, 4 rows per CTA;
// layer 2 has one thread per (row, col).
// ---------------------------------------------------------------------------
__global__ __launch_bounds__(256) void head_kernel(
    const float* __restrict__ W2, const float* __restrict__ b2,
    const float* __restrict__ W3, const float* __restrict__ b3,
    float* __restrict__ out)
{
    __shared__ float h1s[4][H1];
    __shared__ float h2s[4][H2];

    const int b0  = blockIdx.x * 4;
    const int tid = threadIdx.x;

    // load 4 h1 rows (1024 floats) as float4
    {
        const float4* __restrict__ src =
            reinterpret_cast<const float4*>(g_h1 + (size_t)b0 * H1);
        reinterpret_cast<float4*>(&h1s[0][0])[tid] = src[tid];
    }
    __syncthreads();

    // layer 2: thread -> (row i = tid>>6, col j = tid&63)
    {
        const int j = tid & (H2-1);
        const int i = tid >> 6;
        float a = 0.f;
        #pragma unroll 8
        for (int k = 0; k < H1; ++k)
            a = fmaf(h1s[i][k], W2[k*H2 + j], a);
        h2s[i][j] = fmaxf(a + b2[j], 0.f);
    }
    __syncthreads();

    // layer 3 + softmax
    if (tid < 4) {
        const int i = tid;
        float l0 = b3[0], l1 = b3[1], l2 = b3[2], l3 = b3[3];
        #pragma unroll 8
        for (int k = 0; k < H2; ++k) {
            const float h = h2s[i][k];
            l0 = fmaf(h, W3[k*NC+0], l0);
            l1 = fmaf(h, W3[k*NC+1], l1);
            l2 = fmaf(h, W3[k*NC+2], l2);
            l3 = fmaf(h, W3[k*NC+3], l3);
        }
        float m = fmaxf(fmaxf(l0,l1), fmaxf(l2,l3));
        float e0 = expf(l0 - m), e1x = expf(l1 - m),
              e2x = expf(l2 - m), e3 = expf(l3 - m);
        float inv = 1.f / (e0 + e1x + e2x + e3);
        float* o = out + (size_t)(b0 + i) * NC;
        o[0] = e0*inv; o[1] = e1x*inv; o[2] = e2x*inv; o[3] = e3*inv;
    }
}

// ---------------------------------------------------------------------------
extern "C" void kernel_launch(void* const* d_in, const int* in_sizes, int n_in,
                              void* d_out, int out_size)
{
    const float* x   = (const float*)d_in[0];
    const int*   e1  = (const int*)  d_in[1];
    const int*   e2  = (const int*)  d_in[2];
    const float* W1  = (const float*)d_in[3];
    const float* b1  = (const float*)d_in[4];
    const float* W2  = (const float*)d_in[5];
    const float* b2  = (const float*)d_in[6];
    const float* W3  = (const float*)d_in[7];
    const float* b3  = (const float*)d_in[8];
    float* out = (float*)d_out;

    static int smem_set = 0;
    const int gemm_smem = (MT*AS + H1*BS) * (int)sizeof(__nv_bfloat16);  // 104448
    if (!smem_set) {
        cudaFuncSetAttribute(gemm_kernel,
            cudaFuncAttributeMaxDynamicSharedMemorySize, gemm_smem);
        smem_set = 1;
    }

    feat_kernel<<<BB, FNT>>>(x, e1, e2);
    wconv_kernel<<<dim3(FF/64, H1/64), 256>>>(W1);
    gemm_kernel<<<dim3(MTILES, KSPLIT), 512, gemm_smem>>>();
    reduce_kernel<<<BB, 256>>>(b1);
    head_kernel<<<BB/4, 256>>>(W2, b2, W3, b3, out);
}